// round 1
// baseline (speedup 1.0000x reference)
#include <cuda_runtime.h>

#define DIM   1024
#define BATCH 64
#define LOG2E 1.44269504f

// ---- scratch (device globals: no allocations allowed) ----
__device__ float g_qp[BATCH * DIM];
__device__ float g_kp[BATCH * DIM];
__device__ float g_g2[BATCH * DIM];
__device__ float g_w1s[DIM];

__device__ __forceinline__ float ex2f_(float x) {
    float y; asm("ex2.approx.ftz.f32 %0, %1;" : "=f"(y) : "f"(x)); return y;
}
__device__ __forceinline__ float rcpf_(float x) {
    float y; asm("rcp.approx.ftz.f32 %0, %1;" : "=f"(y) : "f"(x)); return y;
}

// ---------------------------------------------------------------------------
// w1_row_sum[r] = sum_c Wg[r, c] for c < DIM   (Wg is [DIM, 2*DIM] row-major)
// warp-per-row; 128 blocks x 8 warps = 1024 rows
// ---------------------------------------------------------------------------
__global__ void w1s_kernel(const float* __restrict__ Wg) {
    int warp = threadIdx.x >> 5, lane = threadIdx.x & 31;
    int row  = blockIdx.x * 8 + warp;
    const float* p = Wg + (size_t)row * (2 * DIM);
    float s = 0.f;
    #pragma unroll 8
    for (int t = 0; t < DIM / 32; t++) s += p[lane + 32 * t];
    #pragma unroll
    for (int o = 16; o > 0; o >>= 1) s += __shfl_xor_sync(0xffffffffu, s, o);
    if (lane == 0) g_w1s[row] = s;
}

// ---------------------------------------------------------------------------
// out[b, i] = sum_k in[b,k] * W[i*ldw + k] + bias[i]
// 128 threads, tile 64b x 16i, K-tile 32, micro-tile 2b x 4i
// ---------------------------------------------------------------------------
__device__ __forceinline__ void gemm_tile(const float* __restrict__ in,
                                          const float* __restrict__ W, int ldw,
                                          const float* __restrict__ bias,
                                          float* __restrict__ out, int i_base)
{
    __shared__ float as[32][66];   // [kk][b], pad 2 -> float2 reads stay aligned
    __shared__ float ws[32][20];   // [kk][i_local], pad 4 -> float4 aligned
    int tid = threadIdx.x;
    int bi = tid & 31;    // b0 = bi*2
    int ii = tid >> 5;    // i0 = ii*4  (0..3)
    float acc[2][4];
    #pragma unroll
    for (int r = 0; r < 2; r++)
        #pragma unroll
        for (int c = 0; c < 4; c++) acc[r][c] = 0.f;

    for (int kt = 0; kt < DIM; kt += 32) {
        #pragma unroll
        for (int r = 0; r < 4; r++) {
            int f = tid + 128 * r;
            int b = f >> 3, k4 = (f & 7) * 4;
            float4 v = *(const float4*)(in + (size_t)b * DIM + kt + k4);
            as[k4 + 0][b] = v.x; as[k4 + 1][b] = v.y;
            as[k4 + 2][b] = v.z; as[k4 + 3][b] = v.w;
        }
        {
            int iL = tid >> 3, k4 = (tid & 7) * 4;
            float4 v = *(const float4*)(W + (size_t)(i_base + iL) * ldw + kt + k4);
            ws[k4 + 0][iL] = v.x; ws[k4 + 1][iL] = v.y;
            ws[k4 + 2][iL] = v.z; ws[k4 + 3][iL] = v.w;
        }
        __syncthreads();
        #pragma unroll
        for (int kk = 0; kk < 32; kk++) {
            float2 a = *(const float2*)&as[kk][bi * 2];
            float4 w = *(const float4*)&ws[kk][ii * 4];
            acc[0][0] = fmaf(a.x, w.x, acc[0][0]);
            acc[0][1] = fmaf(a.x, w.y, acc[0][1]);
            acc[0][2] = fmaf(a.x, w.z, acc[0][2]);
            acc[0][3] = fmaf(a.x, w.w, acc[0][3]);
            acc[1][0] = fmaf(a.y, w.x, acc[1][0]);
            acc[1][1] = fmaf(a.y, w.y, acc[1][1]);
            acc[1][2] = fmaf(a.y, w.z, acc[1][2]);
            acc[1][3] = fmaf(a.y, w.w, acc[1][3]);
        }
        __syncthreads();
    }
    #pragma unroll
    for (int r = 0; r < 2; r++)
        #pragma unroll
        for (int c = 0; c < 4; c++)
            out[(size_t)(bi * 2 + r) * DIM + i_base + ii * 4 + c] =
                acc[r][c] + bias[i_base + ii * 4 + c];
}

__global__ void proj_kernel(const float* __restrict__ q, const float* __restrict__ Wq,
                            const float* __restrict__ bq,
                            const float* __restrict__ k, const float* __restrict__ Wk,
                            const float* __restrict__ bk)
{
    if (blockIdx.y == 0) gemm_tile(q, Wq, DIM, bq, g_qp, blockIdx.x * 16);
    else                 gemm_tile(k, Wk, DIM, bk, g_kp, blockIdx.x * 16);
}

// g2[b,j] = sum_m kp[b,m] * Wg[j, DIM + m] + bg[j]
__global__ void g2_kernel(const float* __restrict__ Wg, const float* __restrict__ bg)
{
    gemm_tile(g_kp, Wg + DIM, 2 * DIM, bg, g_g2, blockIdx.x * 16);
}

// ---------------------------------------------------------------------------
// Fused gate + scores + softmax.
// grid (32, 64): blockIdx.y = batch, blockIdx.x = 32-row i-tile.
// 256 threads = 4 groups of 64 lanes; each group owns a row (2 warps/row),
// 16 j-elements per lane held in registers. kp/g2/w1s pre-scaled by +/-log2e
// and kept in registers across the 8 rows this group processes.
// No max-subtraction: |qp*kp*gate| <~ 5, exp() is fp32-safe.
// ---------------------------------------------------------------------------
__device__ __forceinline__ float elem_(float qp, float w1s_s, float g2_s,
                                       float kp_s, float& sum)
{
    float gp   = fmaf(qp, w1s_s, g2_s);            // -log2e * gate_pre
    float s1   = rcpf_(1.f + ex2f_(gp));           // sigmoid(gate_pre)
    float gate = rcpf_(1.f + ex2f_(s1 * -LOG2E));  // sigmoid(sigmoid(...))
    float e    = ex2f_(qp * kp_s * gate);          // exp(score * gate)
    sum += e;
    return e;
}

__global__ __launch_bounds__(256) void attn_kernel(float* __restrict__ out)
{
    int tid   = threadIdx.x;
    int group = tid >> 6;      // 0..3
    int gl    = tid & 63;      // lane within 64-lane group
    int warp  = tid >> 5;      // 0..7
    int lane  = tid & 31;
    int b     = blockIdx.y;

    const float4* kp4  = (const float4*)(g_kp + (size_t)b * DIM);
    const float4* g24  = (const float4*)(g_g2 + (size_t)b * DIM);
    const float4* w1s4 = (const float4*)g_w1s;

    float4 kps[4], g2s[4], w1ss[4];
    #pragma unroll
    for (int t = 0; t < 4; t++) {
        int idx = t * 64 + gl;
        float4 kv = kp4[idx];
        kps[t].x = kv.x * LOG2E;  kps[t].y = kv.y * LOG2E;
        kps[t].z = kv.z * LOG2E;  kps[t].w = kv.w * LOG2E;
        float4 gv = g24[idx];
        g2s[t].x = gv.x * -LOG2E; g2s[t].y = gv.y * -LOG2E;
        g2s[t].z = gv.z * -LOG2E; g2s[t].w = gv.w * -LOG2E;
        float4 wv = w1s4[idx];
        w1ss[t].x = wv.x * -LOG2E; w1ss[t].y = wv.y * -LOG2E;
        w1ss[t].z = wv.z * -LOG2E; w1ss[t].w = wv.w * -LOG2E;
    }

    __shared__ float s_part[2][8];

    const float* qp_row = g_qp + (size_t)b * DIM;
    int i0 = blockIdx.x * 32 + group;

    for (int r = 0; r < 8; r++) {
        int i = i0 + r * 4;
        float qp = __ldg(qp_row + i);
        float sum = 0.f;
        float4 ev[4];
        #pragma unroll
        for (int t = 0; t < 4; t++) {
            ev[t].x = elem_(qp, w1ss[t].x, g2s[t].x, kps[t].x, sum);
            ev[t].y = elem_(qp, w1ss[t].y, g2s[t].y, kps[t].y, sum);
            ev[t].z = elem_(qp, w1ss[t].z, g2s[t].z, kps[t].z, sum);
            ev[t].w = elem_(qp, w1ss[t].w, g2s[t].w, kps[t].w, sum);
        }
        #pragma unroll
        for (int o = 16; o > 0; o >>= 1) sum += __shfl_xor_sync(0xffffffffu, sum, o);
        if (lane == 0) s_part[r & 1][warp] = sum;
        __syncthreads();
        float tot  = s_part[r & 1][group * 2] + s_part[r & 1][group * 2 + 1];
        float rinv = rcpf_(tot);

        float4* o4 = (float4*)out + (size_t)(b * DIM + i) * (DIM / 4);
        #pragma unroll
        for (int t = 0; t < 4; t++) {
            float4 o;
            o.x = ev[t].x * rinv; o.y = ev[t].y * rinv;
            o.z = ev[t].z * rinv; o.w = ev[t].w * rinv;
            o4[t * 64 + gl] = o;
        }
    }
}

// ---------------------------------------------------------------------------
extern "C" void kernel_launch(void* const* d_in, const int* in_sizes, int n_in,
                              void* d_out, int out_size)
{
    const float* q  = (const float*)d_in[0];
    const float* k  = (const float*)d_in[1];
    // d_in[2] = v : unused by the reference math
    const float* Wq = (const float*)d_in[3];
    const float* bq = (const float*)d_in[4];
    const float* Wk = (const float*)d_in[5];
    const float* bk = (const float*)d_in[6];
    const float* Wg = (const float*)d_in[7];
    const float* bg = (const float*)d_in[8];
    float* out = (float*)d_out;

    w1s_kernel <<<128, 256>>>(Wg);
    proj_kernel<<<dim3(64, 2), 128>>>(q, Wq, bq, k, Wk, bk);
    g2_kernel  <<<64, 128>>>(Wg, bg);
    attn_kernel<<<dim3(32, 64), 256>>>(out);
}

// round 2
// speedup vs baseline: 2.1772x; 2.1772x over previous
#include <cuda_runtime.h>

#define DIM   1024
#define BATCH 64
#define LOG2E 1.44269504f

// ---- scratch (device globals: no allocations allowed) ----
__device__ float g_qp[BATCH * DIM];
__device__ float g_kp[BATCH * DIM];
__device__ float g_g2[BATCH * DIM];
__device__ float g_w1s[DIM];

__device__ __forceinline__ float ex2f_(float x) {
    float y; asm("ex2.approx.ftz.f32 %0, %1;" : "=f"(y) : "f"(x)); return y;
}
__device__ __forceinline__ float rcpf_(float x) {
    float y; asm("rcp.approx.ftz.f32 %0, %1;" : "=f"(y) : "f"(x)); return y;
}
__device__ __forceinline__ float tanhf_(float x) {
    float y; asm("tanh.approx.f32 %0, %1;" : "=f"(y) : "f"(x)); return y;
}

// ---------------------------------------------------------------------------
// Dot-product GEMM: out[m, i_global] = sum_k A[m,k] * W[i*ldw + k] + bias[i]
// 256 threads / block. Block bb covers 8 m-rows x 32 n-cols (256 blocks per
// 64x1024 output). Each warp: 4m x 8n tile via register dot products over
// K=1024 (lane owns k = lane*4 + 128*kc), then a 31-shfl transpose-reduce so
// lane L ends holding output (m0 + L>>3, n0 + (L&7)).
// ---------------------------------------------------------------------------
__device__ __forceinline__ void gemm_dot(const float* __restrict__ A,
                                         const float* __restrict__ W, int ldw,
                                         const float* __restrict__ bias,
                                         float* __restrict__ out, int bb)
{
    int warp = threadIdx.x >> 5, lane = threadIdx.x & 31;
    int m0 = (bb & 7) * 8 + (warp & 1) * 4;
    int n0 = (bb >> 3) * 32 + (warp >> 1) * 8;

    float v[32];
    #pragma unroll
    for (int t = 0; t < 32; t++) v[t] = 0.f;

    #pragma unroll
    for (int kc = 0; kc < 8; kc++) {
        int k = kc * 128 + lane * 4;
        float4 a[4], b[8];
        #pragma unroll
        for (int i = 0; i < 4; i++)
            a[i] = *(const float4*)(A + (size_t)(m0 + i) * DIM + k);
        #pragma unroll
        for (int j = 0; j < 8; j++)
            b[j] = *(const float4*)(W + (size_t)(n0 + j) * ldw + k);
        #pragma unroll
        for (int i = 0; i < 4; i++)
            #pragma unroll
            for (int j = 0; j < 8; j++) {
                float s = v[i * 8 + j];
                s = fmaf(a[i].x, b[j].x, s);
                s = fmaf(a[i].y, b[j].y, s);
                s = fmaf(a[i].z, b[j].z, s);
                s = fmaf(a[i].w, b[j].w, s);
                v[i * 8 + j] = s;
            }
    }

    // transpose-reduce: after 5 rounds, lane L holds full sum of v[L]
    #pragma unroll
    for (int s = 16; s; s >>= 1) {
        bool hi = (lane & s) != 0;
        #pragma unroll
        for (int i = 0; i < 16; i++) {
            if (i < s) {
                float send = hi ? v[i] : v[i + s];
                float recv = __shfl_xor_sync(0xffffffffu, send, s);
                v[i] = (hi ? v[i + s] : v[i]) + recv;
            }
        }
    }

    int m = m0 + (lane >> 3), n = n0 + (lane & 7);
    out[(size_t)m * DIM + n] = v[0] + bias[n];
}

// ---------------------------------------------------------------------------
// Kernel 1: k_proj (256 blocks) + w1_row_sum (16 blocks)
// ---------------------------------------------------------------------------
__global__ __launch_bounds__(256, 2) void phase1_kernel(
    const float* __restrict__ k, const float* __restrict__ Wk,
    const float* __restrict__ bk, const float* __restrict__ Wg)
{
    int bb = blockIdx.x;
    if (bb < 256) {
        gemm_dot(k, Wk, DIM, bk, g_kp, bb);
    } else {
        int warp = threadIdx.x >> 5, lane = threadIdx.x & 31;
        int base = (bb - 256) * 64;
        #pragma unroll
        for (int it = 0; it < 8; it++) {
            int row = base + it * 8 + warp;
            const float* p = Wg + (size_t)row * (2 * DIM);
            float s = 0.f;
            #pragma unroll 8
            for (int t = 0; t < DIM / 32; t++) s += p[lane + 32 * t];
            #pragma unroll
            for (int o = 16; o > 0; o >>= 1) s += __shfl_xor_sync(0xffffffffu, s, o);
            if (lane == 0) g_w1s[row] = s;
        }
    }
}

// ---------------------------------------------------------------------------
// Kernel 2: q_proj (256 blocks) + g2 = kp @ W2.T + bg (256 blocks)
// ---------------------------------------------------------------------------
__global__ __launch_bounds__(256, 2) void phase2_kernel(
    const float* __restrict__ q, const float* __restrict__ Wq,
    const float* __restrict__ bq,
    const float* __restrict__ Wg, const float* __restrict__ bg)
{
    int bb = blockIdx.x;
    if (bb < 256) gemm_dot(q, Wq, DIM, bq, g_qp, bb);
    else          gemm_dot(g_kp, Wg + DIM, 2 * DIM, bg, g_g2, bb - 256);
}

// ---------------------------------------------------------------------------
// Fused gate + scores + softmax.
// grid (32, 64): blockIdx.y = batch, blockIdx.x = 32-row i-tile.
// 256 threads = 4 groups of 64 lanes; each group owns a row (2 warps/row),
// 16 j-elements per lane in registers; kp/g2/w1s pre-scaled and register-
// resident across the group's 8 rows.
// sigmoid(x) = 0.5 + 0.5*tanh(x/2)  (tanh.approx: 1 MUFU per sigmoid)
// 3 MUFU/elem total. No max-subtraction (|score*gate| <~ 5, fp32-safe).
// ---------------------------------------------------------------------------
__device__ __forceinline__ float elem_(float qp, float w1s_h, float g2_h,
                                       float kp_sh, float& sum)
{
    float qkh  = qp * kp_sh;                       // 0.5*log2e*score
    float gph  = fmaf(qp, w1s_h, g2_h);            // 0.5*gate_pre
    float t1   = tanhf_(gph);                      // s1 = 0.5 + 0.5*t1
    float t2   = tanhf_(fmaf(0.25f, t1, 0.25f));   // tanh(s1/2)
    float e    = ex2f_(fmaf(qkh, t2, qkh));        // exp2(log2e*score*gate)
    sum += e;
    return e;
}

__global__ __launch_bounds__(256) void attn_kernel(float* __restrict__ out)
{
    int tid   = threadIdx.x;
    int group = tid >> 6;      // 0..3
    int gl    = tid & 63;      // lane within 64-lane group
    int warp  = tid >> 5;      // 0..7
    int lane  = tid & 31;
    int b     = blockIdx.y;

    const float4* kp4  = (const float4*)(g_kp + (size_t)b * DIM);
    const float4* g24  = (const float4*)(g_g2 + (size_t)b * DIM);
    const float4* w1s4 = (const float4*)g_w1s;

    const float KS = 0.5f * LOG2E;
    float4 kps[4], g2s[4], w1ss[4];
    #pragma unroll
    for (int t = 0; t < 4; t++) {
        int idx = t * 64 + gl;
        float4 kv = kp4[idx];
        kps[t].x = kv.x * KS;   kps[t].y = kv.y * KS;
        kps[t].z = kv.z * KS;   kps[t].w = kv.w * KS;
        float4 gv = g24[idx];
        g2s[t].x = gv.x * 0.5f; g2s[t].y = gv.y * 0.5f;
        g2s[t].z = gv.z * 0.5f; g2s[t].w = gv.w * 0.5f;
        float4 wv = w1s4[idx];
        w1ss[t].x = wv.x * 0.5f; w1ss[t].y = wv.y * 0.5f;
        w1ss[t].z = wv.z * 0.5f; w1ss[t].w = wv.w * 0.5f;
    }

    __shared__ float s_part[2][8];

    const float* qp_row = g_qp + (size_t)b * DIM;
    int i0 = blockIdx.x * 32 + group;

    for (int r = 0; r < 8; r++) {
        int i = i0 + r * 4;
        float qp = __ldg(qp_row + i);
        float sum = 0.f;
        float4 ev[4];
        #pragma unroll
        for (int t = 0; t < 4; t++) {
            ev[t].x = elem_(qp, w1ss[t].x, g2s[t].x, kps[t].x, sum);
            ev[t].y = elem_(qp, w1ss[t].y, g2s[t].y, kps[t].y, sum);
            ev[t].z = elem_(qp, w1ss[t].z, g2s[t].z, kps[t].z, sum);
            ev[t].w = elem_(qp, w1ss[t].w, g2s[t].w, kps[t].w, sum);
        }
        #pragma unroll
        for (int o = 16; o > 0; o >>= 1) sum += __shfl_xor_sync(0xffffffffu, sum, o);
        if (lane == 0) s_part[r & 1][warp] = sum;
        __syncthreads();
        float tot  = s_part[r & 1][group * 2] + s_part[r & 1][group * 2 + 1];
        float rinv = rcpf_(tot);

        float4* o4 = (float4*)out + (size_t)(b * DIM + i) * (DIM / 4);
        #pragma unroll
        for (int t = 0; t < 4; t++) {
            float4 o;
            o.x = ev[t].x * rinv; o.y = ev[t].y * rinv;
            o.z = ev[t].z * rinv; o.w = ev[t].w * rinv;
            __stcs(&o4[t * 64 + gl], o);
        }
    }
}

// ---------------------------------------------------------------------------
extern "C" void kernel_launch(void* const* d_in, const int* in_sizes, int n_in,
                              void* d_out, int out_size)
{
    const float* q  = (const float*)d_in[0];
    const float* k  = (const float*)d_in[1];
    // d_in[2] = v : unused by the reference math
    const float* Wq = (const float*)d_in[3];
    const float* bq = (const float*)d_in[4];
    const float* Wk = (const float*)d_in[5];
    const float* bk = (const float*)d_in[6];
    const float* Wg = (const float*)d_in[7];
    const float* bg = (const float*)d_in[8];
    float* out = (float*)d_out;

    phase1_kernel<<<272, 256>>>(k, Wk, bk, Wg);
    phase2_kernel<<<512, 256>>>(q, Wq, bq, Wg, bg);
    attn_kernel  <<<dim3(32, 64), 256>>>(out);
}